// round 5
// baseline (speedup 1.0000x reference)
#include <cuda_runtime.h>
#include <cuda_fp16.h>

// out[b,o] = max_k min(x[b,k], w[k,o])  (STE forward == hard max-min)
// x: [B,512] f32 uniform[0,1), w: [512,512] f32, out f32.
//
// Candidate algorithm: out[b,:] is a.s. determined by the top x values of
// row b. Tier-1: x >= 0.875 (~64 cands). Tier-2 extension (x in [0.78,
// 0.875)) only for outputs failing the tier-1 certificate (~3e-4). Exact
// fp32 scan as last resort (any-distribution correctness).
//
// R5 layout: 64 threads/block, one b-row per block, 8 outputs per thread.
// Per candidate each thread does ONE LDG.128 (uint4 = 4 half2 = 8 outputs'
// w values) -> ~5x fewer issued instructions than the LDG.32 version.

#define KDIM 512
#define ODIM 512
#define O2   256          // half2 pairs along o
#define NT   64
#define CUT1 0.875f
#define CUT2 0.78f
#define EPS  1e-3f
#define C1MAX 160
#define C2MAX 160

__device__ __half2 g_wh[KDIM * O2];   // [k][o2]; row = 1KB = 64 uint4

__global__ void packw_kernel(const float* __restrict__ w)
{
    int i = blockIdx.x * blockDim.x + threadIdx.x;    // 131072
    if (i < KDIM * O2) {
        float2 v = reinterpret_cast<const float2*>(w)[i];
        g_wh[i] = __floats2half2_rn(v.x, v.y);
    }
}

__global__ __launch_bounds__(NT)
void maxmin_kernel(const float* __restrict__ x,
                   const float* __restrict__ w,
                   float* __restrict__ out)
{
    __shared__ float xs[KDIM];
    __shared__ uint2 c1[C1MAX];       // {half2-splat(x) bits, k*64 (uint4 idx)}
    __shared__ uint2 c2[C2MAX];
    __shared__ int   s_n1, s_n2, s_ovf;

    const int b   = blockIdx.x;
    const int tid = threadIdx.x;      // owns outputs 8*tid .. 8*tid+7

    if (tid == 0) { s_n1 = 0; s_n2 = 0; s_ovf = 0; }
    __syncthreads();

    // ---- stage x row (fp32, for fallback) + threshold selection ----
    const float4* x4 = reinterpret_cast<const float4*>(x + (size_t)b * KDIM);
#pragma unroll
    for (int j = 0; j < 2; j++) {
        float4 v = x4[tid * 2 + j];
        reinterpret_cast<float4*>(xs)[tid * 2 + j] = v;
        float e[4] = {v.x, v.y, v.z, v.w};
#pragma unroll
        for (int q = 0; q < 4; q++) {
            float xv = e[q];
            if (xv >= CUT2) {
                int k = tid * 8 + j * 4 + q;
                __half   h  = __float2half_rn(xv);
                __half2  h2 = __halves2half2(h, h);
                unsigned hb = *reinterpret_cast<const unsigned*>(&h2);
                if (xv >= CUT1) {
                    int p = atomicAdd(&s_n1, 1);
                    if (p < C1MAX) c1[p] = make_uint2(hb, (unsigned)(k * 64));
                    else           s_ovf = 1;
                } else {
                    int p = atomicAdd(&s_n2, 1);
                    if (p < C2MAX) c2[p] = make_uint2(hb, (unsigned)(k * 64));
                    else           s_ovf = 1;
                }
            }
        }
    }
    __syncthreads();

    const int cnt1 = s_n1;
    const int cnt2 = (s_n2 < C2MAX) ? s_n2 : C2MAX;
    const int ovf  = s_ovf;

    const uint4* wq = reinterpret_cast<const uint4*>(g_wh);

    __half2 a0 = __float2half2_rn(0.0f);   // inputs >= 0: 0 is a safe -inf
    __half2 a1 = a0, a2 = a0, a3 = a0;

    if (!ovf) {
        int t = 0;
        for (; t + 8 <= cnt1; t += 8) {    // MLP=8 LDG.128 batches
            uint4    wv[8];
            unsigned xb[8];
#pragma unroll
            for (int u = 0; u < 8; u++) {
                uint2 c = c1[t + u];
                xb[u] = c.x;
                wv[u] = wq[c.y + tid];
            }
#pragma unroll
            for (int u = 0; u < 8; u++) {
                __half2 xv = *reinterpret_cast<__half2*>(&xb[u]);
                a0 = __hmax2(a0, __hmin2(xv, *reinterpret_cast<__half2*>(&wv[u].x)));
                a1 = __hmax2(a1, __hmin2(xv, *reinterpret_cast<__half2*>(&wv[u].y)));
                a2 = __hmax2(a2, __hmin2(xv, *reinterpret_cast<__half2*>(&wv[u].z)));
                a3 = __hmax2(a3, __hmin2(xv, *reinterpret_cast<__half2*>(&wv[u].w)));
            }
        }
        for (; t < cnt1; t++) {
            uint2 c = c1[t];
            uint4 wv = wq[c.y + tid];
            __half2 xv = *reinterpret_cast<__half2*>(&c.x);
            a0 = __hmax2(a0, __hmin2(xv, *reinterpret_cast<__half2*>(&wv.x)));
            a1 = __hmax2(a1, __hmin2(xv, *reinterpret_cast<__half2*>(&wv.y)));
            a2 = __hmax2(a2, __hmin2(xv, *reinterpret_cast<__half2*>(&wv.z)));
            a3 = __hmax2(a3, __hmin2(xv, *reinterpret_cast<__half2*>(&wv.w)));
        }
    }

    float r[8];
    r[0] = __low2float(a0); r[1] = __high2float(a0);
    r[2] = __low2float(a1); r[3] = __high2float(a1);
    r[4] = __low2float(a2); r[5] = __high2float(a2);
    r[6] = __low2float(a3); r[7] = __high2float(a3);

    // ---- tier-2 extension (rare; trigger if ANY of 8 outputs fails cert) ----
    bool fail1 = false;
#pragma unroll
    for (int j = 0; j < 8; j++) fail1 |= (r[j] < CUT1 + EPS);

    if (!ovf && fail1) {
        for (int t = 0; t < cnt2; t++) {
            uint2 c = c2[t];
            uint4 wv = wq[c.y + tid];
            __half2 xv = *reinterpret_cast<__half2*>(&c.x);
            a0 = __hmax2(a0, __hmin2(xv, *reinterpret_cast<__half2*>(&wv.x)));
            a1 = __hmax2(a1, __hmin2(xv, *reinterpret_cast<__half2*>(&wv.y)));
            a2 = __hmax2(a2, __hmin2(xv, *reinterpret_cast<__half2*>(&wv.z)));
            a3 = __hmax2(a3, __hmin2(xv, *reinterpret_cast<__half2*>(&wv.w)));
        }
        r[0] = __low2float(a0); r[1] = __high2float(a0);
        r[2] = __low2float(a1); r[3] = __high2float(a1);
        r[4] = __low2float(a2); r[5] = __high2float(a2);
        r[6] = __low2float(a3); r[7] = __high2float(a3);
    }

    // ---- exact fp32 fallback (essentially never for uniform data) ----
#pragma unroll
    for (int j = 0; j < 8; j++) {
        if (ovf || r[j] < CUT2 + EPS) {
            int o = tid * 8 + j;
            float rr = 0.0f;
#pragma unroll 4
            for (int k = 0; k < KDIM; k++)
                rr = fmaxf(rr, fminf(xs[k], w[(size_t)k * ODIM + o]));
            r[j] = rr;
        }
    }

    float4* op = reinterpret_cast<float4*>(out + (size_t)b * ODIM + tid * 8);
    op[0] = make_float4(r[0], r[1], r[2], r[3]);
    op[1] = make_float4(r[4], r[5], r[6], r[7]);
}

extern "C" void kernel_launch(void* const* d_in, const int* in_sizes, int n_in,
                              void* d_out, int out_size)
{
    const float* x = (const float*)d_in[0];   // [B, 512]
    const float* w = (const float*)d_in[1];   // [512, 512]
    float* out = (float*)d_out;

    int B = in_sizes[0] / KDIM;               // 1024

    packw_kernel<<<(KDIM * O2 + 255) / 256, 256>>>(w);
    maxmin_kernel<<<B, NT>>>(x, w, out);
}

// round 6
// speedup vs baseline: 1.2965x; 1.2965x over previous
#include <cuda_runtime.h>
#include <cuda_fp16.h>

// out[b,o] = max_k min(x[b,k], w[k,o])  (STE forward == hard max-min)
// x: [B,512] f32 uniform[0,1), w: [512,512] f32, out f32.
//
// Candidate algorithm: out[b,:] is a.s. determined by the top x values of
// row b. Tier-1: x >= 0.875 (~64 cands, P(cert fail)=e^-8~3e-4). Tier-2
// extension (x in [0.78, 0.875)) for cert failures. Exact fp32 scan as the
// last resort (any-distribution correctness; never for uniform).
//
// R6 layout: 128 threads/block, one b-row per block, 4 outputs/thread via
// LDG.64 gathers. 4096 warps total (27.7/SM) with ~7 instr per candidate
// per thread: balances issue floor (~2.2us) against latency hiding.

#define KDIM 512
#define ODIM 512
#define O2   256          // half2 pairs along o
#define NT   128          // threads/block; thread owns outputs [4t, 4t+4)
#define CUT1 0.875f
#define CUT2 0.78f
#define EPS  1e-3f
#define C1MAX 160
#define C2MAX 160

__device__ __half2 g_wh[KDIM * O2];   // [k][o2]; row = 1KB = 128 uint2

__global__ void packw_kernel(const float* __restrict__ w)
{
    int i = blockIdx.x * blockDim.x + threadIdx.x;    // 131072
    if (i < KDIM * O2) {
        float2 v = reinterpret_cast<const float2*>(w)[i];
        g_wh[i] = __floats2half2_rn(v.x, v.y);
    }
}

__global__ __launch_bounds__(NT)
void maxmin_kernel(const float* __restrict__ x,
                   const float* __restrict__ w,
                   float* __restrict__ out)
{
    __shared__ float xs[KDIM];
    __shared__ uint2 c1[C1MAX];       // {half2-splat(x) bits, k*128 (uint2 idx)}
    __shared__ uint2 c2[C2MAX];
    __shared__ int   s_n1, s_n2, s_ovf;

    const int b   = blockIdx.x;
    const int tid = threadIdx.x;      // owns outputs 4*tid .. 4*tid+3

    if (tid == 0) { s_n1 = 0; s_n2 = 0; s_ovf = 0; }
    __syncthreads();

    // ---- stage x row (fp32, for fallback) + threshold selection ----
    {
        float4 v = reinterpret_cast<const float4*>(x + (size_t)b * KDIM)[tid];
        reinterpret_cast<float4*>(xs)[tid] = v;
        float e[4] = {v.x, v.y, v.z, v.w};
#pragma unroll
        for (int q = 0; q < 4; q++) {
            float xv = e[q];
            if (xv >= CUT2) {
                int k = tid * 4 + q;
                __half   h  = __float2half_rn(xv);
                __half2  h2 = __halves2half2(h, h);
                unsigned hb = *reinterpret_cast<const unsigned*>(&h2);
                if (xv >= CUT1) {
                    int p = atomicAdd(&s_n1, 1);
                    if (p < C1MAX) c1[p] = make_uint2(hb, (unsigned)(k * 128));
                    else           s_ovf = 1;
                } else {
                    int p = atomicAdd(&s_n2, 1);
                    if (p < C2MAX) c2[p] = make_uint2(hb, (unsigned)(k * 128));
                    else           s_ovf = 1;
                }
            }
        }
    }
    __syncthreads();

    const int cnt1 = s_n1;
    const int cnt2 = (s_n2 < C2MAX) ? s_n2 : C2MAX;
    const int ovf  = s_ovf;

    const uint2* wu = reinterpret_cast<const uint2*>(g_wh);

    __half2 a0 = __float2half2_rn(0.0f);   // inputs >= 0: 0 is a safe -inf
    __half2 a1 = a0;

    if (!ovf) {
        int t = 0;
        for (; t + 8 <= cnt1; t += 8) {    // MLP=8 LDG.64 batches
            uint2    wv[8];
            unsigned xb[8];
#pragma unroll
            for (int u = 0; u < 8; u++) {
                uint2 c = c1[t + u];       // broadcast LDS.64
                xb[u] = c.x;
                wv[u] = wu[c.y + tid];     // LDG.64
            }
#pragma unroll
            for (int u = 0; u < 8; u++) {
                __half2 xv = *reinterpret_cast<__half2*>(&xb[u]);
                a0 = __hmax2(a0, __hmin2(xv, *reinterpret_cast<__half2*>(&wv[u].x)));
                a1 = __hmax2(a1, __hmin2(xv, *reinterpret_cast<__half2*>(&wv[u].y)));
            }
        }
        for (; t < cnt1; t++) {
            uint2 c = c1[t];
            uint2 wv = wu[c.y + tid];
            __half2 xv = *reinterpret_cast<__half2*>(&c.x);
            a0 = __hmax2(a0, __hmin2(xv, *reinterpret_cast<__half2*>(&wv.x)));
            a1 = __hmax2(a1, __hmin2(xv, *reinterpret_cast<__half2*>(&wv.y)));
        }
    }

    float r[4];
    r[0] = __low2float(a0); r[1] = __high2float(a0);
    r[2] = __low2float(a1); r[3] = __high2float(a1);

    // ---- tier-2 extension (rare; trigger if ANY of 4 outputs fails cert) ----
    bool fail1 = false;
#pragma unroll
    for (int j = 0; j < 4; j++) fail1 |= (r[j] < CUT1 + EPS);

    if (!ovf && fail1) {
        for (int t = 0; t < cnt2; t++) {
            uint2 c = c2[t];
            uint2 wv = wu[c.y + tid];
            __half2 xv = *reinterpret_cast<__half2*>(&c.x);
            a0 = __hmax2(a0, __hmin2(xv, *reinterpret_cast<__half2*>(&wv.x)));
            a1 = __hmax2(a1, __hmin2(xv, *reinterpret_cast<__half2*>(&wv.y)));
        }
        r[0] = __low2float(a0); r[1] = __high2float(a0);
        r[2] = __low2float(a1); r[3] = __high2float(a1);
    }

    // ---- exact fp32 fallback (essentially never for uniform data) ----
#pragma unroll
    for (int j = 0; j < 4; j++) {
        if (ovf || r[j] < CUT2 + EPS) {
            int o = tid * 4 + j;
            float rr = 0.0f;
#pragma unroll 4
            for (int k = 0; k < KDIM; k++)
                rr = fmaxf(rr, fminf(xs[k], w[(size_t)k * ODIM + o]));
            r[j] = rr;
        }
    }

    reinterpret_cast<float4*>(out + (size_t)b * ODIM)[tid] =
        make_float4(r[0], r[1], r[2], r[3]);
}

extern "C" void kernel_launch(void* const* d_in, const int* in_sizes, int n_in,
                              void* d_out, int out_size)
{
    const float* x = (const float*)d_in[0];   // [B, 512]
    const float* w = (const float*)d_in[1];   // [512, 512]
    float* out = (float*)d_out;

    int B = in_sizes[0] / KDIM;               // 1024

    packw_kernel<<<(KDIM * O2 + 255) / 256, 256>>>(w);
    maxmin_kernel<<<B, NT>>>(x, w, out);
}